// round 2
// baseline (speedup 1.0000x reference)
#include <cuda_runtime.h>
#include <stdint.h>

// Problem shape (static)
#define B 32
#define L 4
#define S 512
#define D 768
#define G 24   // NUM_SEGMENTS

// Output layout (float32, tuple order concat):
//   word  [B,S,D]  at 0
//   sent  [B,D]    at OFF_SENT
//   seg   [B,G,D]  at OFF_SEG
//   mask  [B,G]    at OFF_MASK
#define OFF_SENT ((size_t)B * S * D)                 // 12,582,912
#define OFF_SEG  (OFF_SENT + (size_t)B * D)          // 12,607,488
#define OFF_MASK (OFF_SEG + (size_t)B * G * D)       // 13,197,312

// grid: (6 d-slices, 32 batches), block: 128 threads (each thread owns one d column)
__global__ void __launch_bounds__(128, 2)
bert_agg_kernel(const float* __restrict__ emb,
                const int*   __restrict__ tg,
                const int*   __restrict__ sg,
                float*       __restrict__ out)
{
    const int b = blockIdx.y;
    const int d = blockIdx.x * 128 + threadIdx.x;

    __shared__ int s_tg[S];
    __shared__ int s_sg[S];
    for (int i = threadIdx.x; i < S; i += 128) {
        s_tg[i] = tg[b * S + i];
        s_sg[i] = sg[b * S + i];
    }
    __syncthreads();

    const float* ep   = emb + ((size_t)b * L * S) * D + d;
    float*       wout = out + ((size_t)b * S) * D + d;
    float*       gout = out + OFF_SEG + ((size_t)b * G) * D + d;

    // layer strides in floats
    const size_t LS = (size_t)S * D;   // 393216

    float sent = 0.f;

    int   cur_g  = s_tg[0];
    float wacc   = 0.f;
    int   cur_sg = s_sg[cur_g];
    float gacc   = 0.f;

    // zero leading (never-hit) word slots and segment slots
    for (int z = 0; z < cur_g; ++z)  wout[(size_t)z * D] = 0.f;
    for (int z = 0; z < cur_sg; ++z) gout[(size_t)z * D] = 0.f;

    // ---- double-buffered streaming over tokens, 8 tokens x 4 layers per chunk ----
    float v0[8], v1[8], v2[8], v3[8];
#pragma unroll
    for (int i = 0; i < 8; ++i) {
        const float* p = ep + (size_t)i * D;
        v0[i] = p[0];
        v1[i] = p[LS];
        v2[i] = p[2 * LS];
        v3[i] = p[3 * LS];
    }

#pragma unroll 1
    for (int tc = 0; tc < S; tc += 8) {
        float e[8];
#pragma unroll
        for (int i = 0; i < 8; ++i)
            e[i] = (v0[i] + v1[i]) + (v2[i] + v3[i]);

        // prefetch next chunk (loads in flight during the run-length logic below)
        const int tn = tc + 8;
        if (tn < S) {
#pragma unroll
            for (int i = 0; i < 8; ++i) {
                const float* p = ep + (size_t)(tn + i) * D;
                v0[i] = p[0];
                v1[i] = p[LS];
                v2[i] = p[2 * LS];
                v3[i] = p[3 * LS];
            }
        }

        // run-length flush logic (block-uniform control flow)
#pragma unroll
        for (int i = 0; i < 8; ++i) {
            const int g = s_tg[tc + i];
            if (g != cur_g) {
                // flush word slot cur_g
                wout[(size_t)cur_g * D] = wacc;
                // feed it into the segment accumulator
                const int mysg = s_sg[cur_g];
                if (mysg != cur_sg) {
                    gout[(size_t)cur_sg * D] = gacc;
                    for (int z = cur_sg + 1; z < mysg; ++z)
                        gout[(size_t)z * D] = 0.f;
                    gacc = 0.f;
                    cur_sg = mysg;
                }
                gacc += wacc;
                // zero skipped word slots
                for (int z = cur_g + 1; z < g; ++z)
                    wout[(size_t)z * D] = 0.f;
                wacc  = 0.f;
                cur_g = g;
            }
            wacc += e[i];
            sent += e[i];
        }
    }

    // ---- final flushes ----
    wout[(size_t)cur_g * D] = wacc;
    {
        const int mysg = s_sg[cur_g];
        if (mysg != cur_sg) {
            gout[(size_t)cur_sg * D] = gacc;
            for (int z = cur_sg + 1; z < mysg; ++z)
                gout[(size_t)z * D] = 0.f;
            gacc = 0.f;
            cur_sg = mysg;
        }
        gacc += wacc;
    }
    for (int z = cur_g + 1; z < S; ++z)
        wout[(size_t)z * D] = 0.f;

    gout[(size_t)cur_sg * D] = gacc;
    for (int z = cur_sg + 1; z < G; ++z)
        gout[(size_t)z * D] = 0.f;

    // sentence embedding: mean over 512 word slots, summed over layers
    out[OFF_SENT + (size_t)b * D + d] = sent * (1.0f / 512.0f);

    // seg_mask (sorted segment_ids -> max is last element)
    if (blockIdx.x == 0 && threadIdx.x < G) {
        const int seg_num = s_sg[S - 1] + 1;
        out[OFF_MASK + (size_t)b * G + threadIdx.x] =
            (threadIdx.x >= seg_num) ? 1.0f : 0.0f;
    }
}

extern "C" void kernel_launch(void* const* d_in, const int* in_sizes, int n_in,
                              void* d_out, int out_size)
{
    const float* emb = (const float*)d_in[0];   // embeddings      [B,L,S,D] f32
    const int*   tg  = (const int*)  d_in[1];   // token_group_ids [B,S] i32
    const int*   sg  = (const int*)  d_in[2];   // segment_ids     [B,S] i32
    float*       out = (float*)d_out;

    dim3 grid(D / 128, B);   // (6, 32)
    bert_agg_kernel<<<grid, 128>>>(emb, tg, sg, out);
}

// round 3
// speedup vs baseline: 1.2847x; 1.2847x over previous
#include <cuda_runtime.h>
#include <stdint.h>

// Problem shape (static)
#define B 32
#define L 4
#define S 512
#define D 768
#define G 24        // NUM_SEGMENTS
#define NCHUNK 8
#define TPC (S / NCHUNK)   // nominal tokens per chunk

// Output layout (float32, tuple-order concat):
//   word [B,S,D] | sent [B,D] | seg [B,G,D] | mask [B,G]
#define OFF_SENT ((size_t)B * S * D)
#define OFF_SEG  (OFF_SENT + (size_t)B * D)
#define OFF_MASK (OFF_SEG + (size_t)B * G * D)
// region that is accumulated with atomics and must start at zero: sent + seg
#define ZERO_N   ((size_t)B * D + (size_t)B * G * D)

__global__ void init_zero_kernel(float* __restrict__ out)
{
    size_t i = (size_t)blockIdx.x * blockDim.x + threadIdx.x;
    if (i < ZERO_N) out[OFF_SENT + i] = 0.f;
}

// grid: (6 d-slices * 8 token-chunks, 32 batches), block: 128 threads (1 d column each)
__global__ void __launch_bounds__(128, 4)
bert_agg_kernel(const float* __restrict__ emb,
                const int*   __restrict__ tg,
                const int*   __restrict__ sg,
                float*       __restrict__ out)
{
    const int b      = blockIdx.y;
    const int chunk  = blockIdx.x / 6;
    const int dslice = blockIdx.x % 6;
    const int d      = dslice * 128 + threadIdx.x;

    __shared__ int s_tg[S];
    __shared__ int s_sg[S];
    for (int i = threadIdx.x; i < S; i += 128) {
        s_tg[i] = tg[b * S + i];
        s_sg[i] = sg[b * S + i];
    }
    __syncthreads();

    // ---- snap chunk boundaries to word-run boundaries (block-uniform) ----
    int ts = chunk * TPC;
    while (ts > 0 && ts < S && s_tg[ts] == s_tg[ts - 1]) ++ts;
    int te;
    if (chunk == NCHUNK - 1) {
        te = S;
    } else {
        te = (chunk + 1) * TPC;
        while (te < S && s_tg[te] == s_tg[te - 1]) ++te;
    }

    const float* ep   = emb + ((size_t)b * L * S) * D + d;
    float*       wout = out + ((size_t)b * S) * D + d;
    float*       gout = out + OFF_SEG + ((size_t)b * G) * D + d;
    const size_t LS   = (size_t)S * D;

    if (ts < te) {
        // leading gap (only chunk whose snapped start is token 0)
        if (ts == 0) {
            const int firstw = s_tg[0];
            for (int z = 0; z < firstw; ++z) wout[(size_t)z * D] = 0.f;
        }

        float sent = 0.f;
        int   cur_g  = s_tg[ts];
        float wacc   = 0.f;
        int   cur_sg = s_sg[cur_g];
        float gacc   = 0.f;

        // ---- double-buffered token stream, 8 tokens x 4 layers in flight ----
        float v0[8], v1[8], v2[8], v3[8];
#pragma unroll
        for (int i = 0; i < 8; ++i) {
            const int t = (ts + i < S) ? (ts + i) : (S - 1);
            const float* p = ep + (size_t)t * D;
            v0[i] = p[0];
            v1[i] = p[LS];
            v2[i] = p[2 * LS];
            v3[i] = p[3 * LS];
        }

#pragma unroll 1
        for (int tc = ts; tc < te; tc += 8) {
            float e[8];
#pragma unroll
            for (int i = 0; i < 8; ++i)
                e[i] = (v0[i] + v1[i]) + (v2[i] + v3[i]);

            const int tn = tc + 8;
            if (tn < te) {
#pragma unroll
                for (int i = 0; i < 8; ++i) {
                    const int t = (tn + i < S) ? (tn + i) : (S - 1);
                    const float* p = ep + (size_t)t * D;
                    v0[i] = p[0];
                    v1[i] = p[LS];
                    v2[i] = p[2 * LS];
                    v3[i] = p[3 * LS];
                }
            }

            const int n = te - tc;   // >= 1; may exceed 8 (use min with 8 via predicate)
#pragma unroll
            for (int i = 0; i < 8; ++i) {
                if (i < n) {
                    const int g = s_tg[tc + i];
                    if (g != cur_g) {
                        // flush completed word run (owned exclusively by this chunk)
                        wout[(size_t)cur_g * D] = wacc;
                        const int mysg = s_sg[cur_g];
                        if (mysg != cur_sg) {
                            if (gacc != 0.f) atomicAdd(&gout[(size_t)cur_sg * D], gacc);
                            gacc   = 0.f;
                            cur_sg = mysg;
                        }
                        gacc += wacc;
                        // zero skipped word slots interior to this chunk's range
                        for (int z = cur_g + 1; z < g; ++z)
                            wout[(size_t)z * D] = 0.f;
                        wacc  = 0.f;
                        cur_g = g;
                    }
                    wacc += e[i];
                    sent += e[i];
                }
            }
        }

        // ---- final flushes ----
        wout[(size_t)cur_g * D] = wacc;
        {
            const int mysg = s_sg[cur_g];
            if (mysg != cur_sg) {
                if (gacc != 0.f) atomicAdd(&gout[(size_t)cur_sg * D], gacc);
                gacc   = 0.f;
                cur_sg = mysg;
            }
            gacc += wacc;
        }
        atomicAdd(&gout[(size_t)cur_sg * D], gacc);

        // trailing word gap owned by this chunk: (last word, first word of next chunk)
        {
            const int lastw = cur_g;
            const int nextw = (te < S) ? s_tg[te] : S;
            for (int z = lastw + 1; z < nextw; ++z)
                wout[(size_t)z * D] = 0.f;
        }

        // sentence partial: mean over 512 padded word slots == total sum / 512
        atomicAdd(&out[OFF_SENT + (size_t)b * D + d], sent * (1.0f / 512.0f));
    }

    // seg_mask (sorted segment_ids -> max is last element); one block per batch
    if (blockIdx.x == 0 && threadIdx.x < G) {
        const int seg_num = s_sg[S - 1] + 1;
        out[OFF_MASK + (size_t)b * G + threadIdx.x] =
            (threadIdx.x >= seg_num) ? 1.0f : 0.0f;
    }
}

extern "C" void kernel_launch(void* const* d_in, const int* in_sizes, int n_in,
                              void* d_out, int out_size)
{
    const float* emb = (const float*)d_in[0];   // embeddings      [B,L,S,D] f32
    const int*   tg  = (const int*)  d_in[1];   // token_group_ids [B,S] i32
    const int*   sg  = (const int*)  d_in[2];   // segment_ids     [B,S] i32
    float*       out = (float*)d_out;

    const int zthreads = 256;
    const int zblocks  = (int)((ZERO_N + zthreads - 1) / zthreads);
    init_zero_kernel<<<zblocks, zthreads>>>(out);

    dim3 grid(6 * NCHUNK, B);   // (48, 32) = 1536 CTAs
    bert_agg_kernel<<<grid, 128>>>(emb, tg, sg, out);
}

// round 4
// speedup vs baseline: 1.4001x; 1.0899x over previous
#include <cuda_runtime.h>
#include <stdint.h>

// Problem shape (static)
#define B 32
#define L 4
#define S 512
#define D 768
#define G 24        // NUM_SEGMENTS
#define NCHUNK 6
#define TPC (S / NCHUNK)   // 85 nominal tokens per chunk

// Output layout (float32, tuple-order concat):
//   word [B,S,D] | sent [B,D] | seg [B,G,D] | mask [B,G]
#define OFF_SENT ((size_t)B * S * D)
#define OFF_SEG  (OFF_SENT + (size_t)B * D)
#define OFF_MASK (OFF_SEG + (size_t)B * G * D)
// region accumulated with atomics -> must start at zero: sent + seg (contiguous)
#define ZERO_N   ((size_t)B * D + (size_t)B * G * D)

// grid: (6 dslices * NCHUNK chunks, 32 batches), block: 128 threads (1 d column each)
__global__ void __launch_bounds__(128, 8)
bert_agg_kernel(const float* __restrict__ emb,
                const int*   __restrict__ tg,
                const int*   __restrict__ sg,
                float*       __restrict__ out)
{
    const int b      = blockIdx.y;
    const int chunk  = blockIdx.x / 6;
    const int dslice = blockIdx.x % 6;
    const int d      = dslice * 128 + threadIdx.x;

    __shared__ int s_tg[S];
    __shared__ int s_sg[S];
    for (int i = threadIdx.x; i < S; i += 128) {
        s_tg[i] = tg[b * S + i];
        s_sg[i] = sg[b * S + i];
    }
    __syncthreads();

    // ---- snap chunk boundaries to word-run boundaries (block-uniform) ----
    int ts = chunk * TPC;
    while (ts > 0 && ts < S && s_tg[ts] == s_tg[ts - 1]) ++ts;
    int te;
    if (chunk == NCHUNK - 1) {
        te = S;
    } else {
        te = (chunk + 1) * TPC;
        while (te < S && s_tg[te] == s_tg[te - 1]) ++te;
    }

    const float* ep   = emb + ((size_t)b * L * S) * D + d;
    float*       wout = out + ((size_t)b * S) * D + d;
    float*       gout = out + OFF_SEG + ((size_t)b * G) * D + d;
    const size_t LS   = (size_t)S * D;

    if (ts < te) {
        // leading word gap (only the chunk whose snapped start is token 0)
        if (ts == 0) {
            const int firstw = s_tg[0];
            for (int z = 0; z < firstw; ++z) wout[(size_t)z * D] = 0.f;
        }

        float sent   = 0.f;
        int   cur_g  = s_tg[ts];
        float wacc   = 0.f;
        int   cur_sg = s_sg[cur_g];
        float gacc   = 0.f;

        // ---- streaming: 4 tokens x 4 layers in flight (16 LDG), prefetch next group ----
        float v0[4], v1[4], v2[4], v3[4];
#pragma unroll
        for (int i = 0; i < 4; ++i) {
            const int t = (ts + i < S) ? (ts + i) : (S - 1);
            const float* p = ep + (size_t)t * D;
            v0[i] = p[0];
            v1[i] = p[LS];
            v2[i] = p[2 * LS];
            v3[i] = p[3 * LS];
        }

#pragma unroll 1
        for (int tc = ts; tc < te; tc += 4) {
            float e[4];
#pragma unroll
            for (int i = 0; i < 4; ++i)
                e[i] = (v0[i] + v1[i]) + (v2[i] + v3[i]);

            const int tn = tc + 4;
            if (tn < te) {
#pragma unroll
                for (int i = 0; i < 4; ++i) {
                    const int t = (tn + i < S) ? (tn + i) : (S - 1);
                    const float* p = ep + (size_t)t * D;
                    v0[i] = p[0];
                    v1[i] = p[LS];
                    v2[i] = p[2 * LS];
                    v3[i] = p[3 * LS];
                }
            }

            const int n = te - tc;
#pragma unroll
            for (int i = 0; i < 4; ++i) {
                if (i < n) {
                    const int g = s_tg[tc + i];
                    if (g != cur_g) {
                        // flush completed word run (owned exclusively by this chunk)
                        wout[(size_t)cur_g * D] = wacc;
                        const int mysg = s_sg[cur_g];
                        if (mysg != cur_sg) {
                            if (gacc != 0.f) atomicAdd(&gout[(size_t)cur_sg * D], gacc);
                            gacc   = 0.f;
                            cur_sg = mysg;
                        }
                        gacc += wacc;
                        // zero skipped word slots interior to this chunk's range
                        for (int z = cur_g + 1; z < g; ++z)
                            wout[(size_t)z * D] = 0.f;
                        wacc  = 0.f;
                        cur_g = g;
                    }
                    wacc += e[i];
                    sent += e[i];
                }
            }
        }

        // ---- final flushes ----
        wout[(size_t)cur_g * D] = wacc;
        {
            const int mysg = s_sg[cur_g];
            if (mysg != cur_sg) {
                if (gacc != 0.f) atomicAdd(&gout[(size_t)cur_sg * D], gacc);
                gacc   = 0.f;
                cur_sg = mysg;
            }
            gacc += wacc;
        }
        atomicAdd(&gout[(size_t)cur_sg * D], gacc);

        // trailing word gap owned by this chunk: (last word, first word of next chunk)
        {
            const int lastw = cur_g;
            const int nextw = (te < S) ? s_tg[te] : S;
            for (int z = lastw + 1; z < nextw; ++z)
                wout[(size_t)z * D] = 0.f;
        }

        // sentence partial: mean over 512 padded word slots == total sum / 512
        atomicAdd(&out[OFF_SENT + (size_t)b * D + d], sent * (1.0f / 512.0f));
    }

    // seg_mask (sorted segment_ids -> max is last element); one block per batch
    if (blockIdx.x == 0 && threadIdx.x < G) {
        const int seg_num = s_sg[S - 1] + 1;
        out[OFF_MASK + (size_t)b * G + threadIdx.x] =
            (threadIdx.x >= seg_num) ? 1.0f : 0.0f;
    }
}

extern "C" void kernel_launch(void* const* d_in, const int* in_sizes, int n_in,
                              void* d_out, int out_size)
{
    const float* emb = (const float*)d_in[0];   // embeddings      [B,L,S,D] f32
    const int*   tg  = (const int*)  d_in[1];   // token_group_ids [B,S] i32
    const int*   sg  = (const int*)  d_in[2];   // segment_ids     [B,S] i32
    float*       out = (float*)d_out;

    // zero the atomically-accumulated region (sent + seg) via a memset node
    cudaMemsetAsync(out + OFF_SENT, 0, ZERO_N * sizeof(float));

    dim3 grid(6 * NCHUNK, B);   // (36, 32) = 1152 CTAs ~= one full wave at occ 8
    bert_agg_kernel<<<grid, 128>>>(emb, tg, sg, out);
}